// round 16
// baseline (speedup 1.0000x reference)
#include <cuda_runtime.h>
#include <math.h>

#define B 8
#define N 256
#define D 128
#define H 256
#define BN (B * N)   // 2048

// Scratch (allocation-free rule: device globals), 16B aligned for vector access
__device__ __align__(16) float g_hi[BN * H];   // slots @ W_m1[:D]
__device__ __align__(16) float g_hj[BN * H];   // slots @ W_m1[D:] + b_m1
__device__ __align__(16) float g_G [BN * H];   // sum_j a_ij * gelu(hi_i + hj_j)
__device__ float g_asum[BN];                   // rowsum(adjacency)

// 2*gelu(x) via the tanh formulation + MUFU tanh.approx (sm_75+)
__device__ __forceinline__ float gelu2_tanh(float x) {
    const float xx = x * x;
    const float inner = fmaf(0.0356774081f, xx, 0.7978845608f);
    const float w = x * inner;
    float t; asm("tanh.approx.f32 %0,%1;" : "=f"(t) : "f"(w));
    return fmaf(x, t, x);                                        // x*(1+t)
}

// ---------------------------------------------------------------------------
// Kernel 0: adjacency row sums. Warp per row.
// ---------------------------------------------------------------------------
__global__ __launch_bounds__(256) void asum_kernel(const float* __restrict__ adj)
{
    const int row  = blockIdx.x * 8 + (threadIdx.x >> 5);  // b*N + n
    const int lane = threadIdx.x & 31;
    const float* arow = adj + (size_t)row * N;
    float s = 0.f;
#pragma unroll
    for (int k = 0; k < 8; ++k) s += arow[lane + k * 32];
#pragma unroll
    for (int o = 16; o > 0; o >>= 1) s += __shfl_xor_sync(~0u, s, o);
    if (lane == 0) g_asum[row] = s;
}

// ---------------------------------------------------------------------------
// Kernel 1: proj GEMM, 64x32 tiles (grid 32x16 = 512 blocks), 256 threads.
// ---------------------------------------------------------------------------
#define KC 32
__global__ __launch_bounds__(256) void proj_kernel(
    const float* __restrict__ slots, const float* __restrict__ W_m1,
    const float* __restrict__ b_m1)
{
    const int r0   = blockIdx.x * 64;
    const int part = blockIdx.y >> 3;        // 0 -> hi, 1 -> hj
    const int c0   = (blockIdx.y & 7) * 32;
    const int tid  = threadIdx.x;
    const int ty   = tid >> 4, tx = tid & 15;

    __shared__ float As[64][KC + 1];
    __shared__ float Ws[KC][33];

    float acc[4][2];
#pragma unroll
    for (int r = 0; r < 4; ++r)
#pragma unroll
        for (int c = 0; c < 2; ++c) acc[r][c] = 0.f;

    const float* wsrc = W_m1 + (size_t)(part * D) * H + c0;

    for (int kc = 0; kc < D; kc += KC) {
#pragma unroll
        for (int l = 0; l < 8; ++l) {
            const int idx = tid + l * 256;
            const int r = idx >> 5, k = idx & 31;
            As[r][k] = slots[(r0 + r) * D + kc + k];
        }
#pragma unroll
        for (int l = 0; l < 4; ++l) {
            const int idx = tid + l * 256;
            const int k = idx >> 5, c = idx & 31;
            Ws[k][c] = wsrc[(kc + k) * H + c];
        }
        __syncthreads();

#pragma unroll
        for (int k = 0; k < KC; ++k) {
            float wv[2], av[4];
#pragma unroll
            for (int c = 0; c < 2; ++c) wv[c] = Ws[k][tx + 16 * c];
#pragma unroll
            for (int r = 0; r < 4; ++r) av[r] = As[ty + 16 * r][k];
#pragma unroll
            for (int r = 0; r < 4; ++r)
#pragma unroll
                for (int c = 0; c < 2; ++c)
                    acc[r][c] = fmaf(av[r], wv[c], acc[r][c]);
        }
        __syncthreads();
    }

    if (part == 0) {
#pragma unroll
        for (int r = 0; r < 4; ++r)
#pragma unroll
            for (int c = 0; c < 2; ++c)
                g_hi[(size_t)(r0 + ty + 16 * r) * H + c0 + tx + 16 * c] = acc[r][c];
    } else {
        float bm[2];
#pragma unroll
        for (int c = 0; c < 2; ++c) bm[c] = b_m1[c0 + tx + 16 * c];
#pragma unroll
        for (int r = 0; r < 4; ++r)
#pragma unroll
            for (int c = 0; c < 2; ++c)
                g_hj[(size_t)(r0 + ty + 16 * r) * H + c0 + tx + 16 * c] = acc[r][c] + bm[c];
    }
}

// ---------------------------------------------------------------------------
// Kernel 2: G[b,i,h] = sum_j a[b,i,j] * gelu(hi[b,i,h] + hjp[b,j,h])
// 2 i-rows per block (grid 1024), 128 threads; thread owns h-pair (2t, 2t+1).
// ---------------------------------------------------------------------------
__global__ __launch_bounds__(128) void msg_agg_kernel(
    const float* __restrict__ adj)
{
    const int row0 = blockIdx.x * 2;
    const int b    = row0 >> 8;
    const int i0   = row0 & (N - 1);
    const int tid  = threadIdx.x;

    __shared__ float a_s[2][N];             // prescaled by 0.5 (gelu2 = 2*gelu)
    const float* adj_b = adj + ((size_t)b * N + i0) * N;
#pragma unroll
    for (int idx = tid; idx < 2 * N; idx += 128)
        ((float*)a_s)[idx] = 0.5f * adj_b[idx];
    __syncthreads();

    const float2* hj2 = (const float2*)(g_hj + (size_t)b * N * H) + tid;
    const float2 hi0 = ((const float2*)(g_hi + (size_t) row0      * H))[tid];
    const float2 hi1 = ((const float2*)(g_hi + (size_t)(row0 + 1) * H))[tid];

    float acc00 = 0.f, acc01 = 0.f, acc10 = 0.f, acc11 = 0.f;

#pragma unroll 4
    for (int j = 0; j < N; ++j) {
        const float2 hj = hj2[(size_t)j * (H / 2)];
        const float a0 = a_s[0][j];
        const float a1 = a_s[1][j];
        acc00 = fmaf(a0, gelu2_tanh(hi0.x + hj.x), acc00);
        acc01 = fmaf(a0, gelu2_tanh(hi0.y + hj.y), acc01);
        acc10 = fmaf(a1, gelu2_tanh(hi1.x + hj.x), acc10);
        acc11 = fmaf(a1, gelu2_tanh(hi1.y + hj.y), acc11);
    }

    float2 o0; o0.x = acc00; o0.y = acc01;
    float2 o1; o1.x = acc10; o1.y = acc11;
    ((float2*)(g_G + (size_t) row0      * H))[tid] = o0;
    ((float2*)(g_G + (size_t)(row0 + 1) * H))[tid] = o1;
}

// ---------------------------------------------------------------------------
// Kernel 3: fused epilogue v4 — R14's transposed + register-blocked structure
// at R=8 rows/block (grid 256 >= 1 full wave; ~2 blocks/SM resident).
//   Phase A: agg = G @ W_m2 + asum*b_m2     (thread: 1 row x 4 cols)
//   Phase C: u = [slots|agg] @ W_u1 + b_u1  (thread: 2 rows x 4 cols)
//   LN + tanh-gelu (warp per row, on transposed u)
//   Phase E: out = slots + u @ W_u2 + b_u2  (thread: 1 row x 4 cols)
// Pitch-9 transposed tiles: gcd(9,32)=1 -> conflict-free column access.
// ---------------------------------------------------------------------------
#define P 9
__global__ __launch_bounds__(256) void epilogue_kernel(
    const float* __restrict__ slots,
    const float* __restrict__ W_m2, const float* __restrict__ b_m2,
    const float* __restrict__ W_u1, const float* __restrict__ b_u1,
    const float* __restrict__ ln_g, const float* __restrict__ ln_b,
    const float* __restrict__ W_u2, const float* __restrict__ b_u2,
    float* __restrict__ out)
{
    const int r0  = blockIdx.x * 8;         // global row = b*N + n
    const int tid = threadIdx.x;
    const int warp = tid >> 5, lane = tid & 31;
    const int hg  = tid & 63;               // phase C: cols 4hg..4hg+3
    const int r2  = tid >> 6;               //          rows 2r2, 2r2+1

    __shared__ __align__(16) float bufA[256 * P]; // G_t -> [slots_t|agg_t]
    __shared__ __align__(16) float bufU[256 * P]; // u_t
    __shared__ __align__(16) float ws[4096];      // 16KB weight staging
    __shared__ float asum_s[8];

    // Load G transposed: bufA[k*P + row]
#pragma unroll
    for (int l = 0; l < 8; ++l) {
        const int idx = tid + l * 256;
        const int row = idx >> 8, k = idx & 255;
        bufA[k * P + row] = g_G[(size_t)(r0 + row) * H + k];
    }
    if (tid < 8) asum_s[tid] = g_asum[r0 + tid];
    __syncthreads();

    // ---- Phase A: agg (K=256, 8 chunks of 32). row=warp, cols 4*lane.. ----
    float accA[4];
    {
#pragma unroll
        for (int c = 0; c < 4; ++c)
            accA[c] = asum_s[warp] * b_m2[4 * lane + c];
        for (int kc = 0; kc < 256; kc += 32) {
#pragma unroll
            for (int l = 0; l < 16; ++l) {
                const int idx = tid + l * 256;
                ws[idx] = W_m2[(size_t)(kc + (idx >> 7)) * D + (idx & 127)];
            }
            __syncthreads();
#pragma unroll 8
            for (int k = 0; k < 32; ++k) {
                const float4 wv = *(const float4*)&ws[k * 128 + 4 * lane];
                const float a = bufA[(kc + k) * P + warp];
                accA[0] = fmaf(a, wv.x, accA[0]);
                accA[1] = fmaf(a, wv.y, accA[1]);
                accA[2] = fmaf(a, wv.z, accA[2]);
                accA[3] = fmaf(a, wv.w, accA[3]);
            }
            __syncthreads();
        }
    }

    // Repack bufA: [k 0..127] = slots_t, [k 128..255] = agg_t
#pragma unroll
    for (int c = 0; c < 4; ++c)
        bufA[(128 + 4 * lane + c) * P + warp] = accA[c];
#pragma unroll
    for (int l = 0; l < 4; ++l) {
        const int idx = tid + l * 256;
        const int row = idx >> 7, dd = idx & 127;
        bufA[dd * P + row] = slots[(size_t)(r0 + row) * D + dd];
    }
    __syncthreads();

    // ---- Phase C: u = [slots|agg] @ W_u1 + b_u1 (K=256, 16 chunks of 16) ----
    float accU[2][4];
    {
#pragma unroll
        for (int c = 0; c < 4; ++c) {
            const float bu = b_u1[4 * hg + c];
            accU[0][c] = bu; accU[1][c] = bu;
        }
        for (int kc = 0; kc < 256; kc += 16) {
#pragma unroll
            for (int l = 0; l < 16; ++l) {
                const int idx = tid + l * 256;
                ws[idx] = W_u1[(size_t)(kc + (idx >> 8)) * H + (idx & 255)];
            }
            __syncthreads();
#pragma unroll 4
            for (int k = 0; k < 16; ++k) {
                const float4 wv = *(const float4*)&ws[k * 256 + 4 * hg];
                const float a0 = bufA[(kc + k) * P + 2 * r2];
                const float a1 = bufA[(kc + k) * P + 2 * r2 + 1];
                accU[0][0] = fmaf(a0, wv.x, accU[0][0]);
                accU[0][1] = fmaf(a0, wv.y, accU[0][1]);
                accU[0][2] = fmaf(a0, wv.z, accU[0][2]);
                accU[0][3] = fmaf(a0, wv.w, accU[0][3]);
                accU[1][0] = fmaf(a1, wv.x, accU[1][0]);
                accU[1][1] = fmaf(a1, wv.y, accU[1][1]);
                accU[1][2] = fmaf(a1, wv.z, accU[1][2]);
                accU[1][3] = fmaf(a1, wv.w, accU[1][3]);
            }
            __syncthreads();
        }
    }
    // store u transposed: bufU[h*P + row]
#pragma unroll
    for (int r = 0; r < 2; ++r)
#pragma unroll
        for (int c = 0; c < 4; ++c)
            bufU[(4 * hg + c) * P + 2 * r2 + r] = accU[r][c];
    __syncthreads();

    // ---- LayerNorm + tanh-gelu: warp per row ----
    {
        const int row = warp;
        float v[8];
#pragma unroll
        for (int m = 0; m < 8; ++m) v[m] = bufU[(lane + 32 * m) * P + row];
        float s = 0.f;
#pragma unroll
        for (int m = 0; m < 8; ++m) s += v[m];
#pragma unroll
        for (int o = 16; o > 0; o >>= 1) s += __shfl_xor_sync(~0u, s, o);
        const float mu = s * (1.f / H);
        float ss = 0.f;
#pragma unroll
        for (int m = 0; m < 8; ++m) { const float dd = v[m] - mu; ss += dd * dd; }
#pragma unroll
        for (int o = 16; o > 0; o >>= 1) ss += __shfl_xor_sync(~0u, ss, o);
        const float rstd = rsqrtf(ss * (1.f / H) + 1e-5f);
#pragma unroll
        for (int m = 0; m < 8; ++m) {
            const int h = lane + 32 * m;
            const float x = (v[m] - mu) * rstd * ln_g[h] + ln_b[h];
            bufU[h * P + row] = 0.5f * gelu2_tanh(x);
        }
    }
    __syncthreads();

    // ---- Phase E: out = slots + u @ W_u2 + b_u2 (K=256, 8 chunks of 32) ----
    float accO[4];
    {
#pragma unroll
        for (int c = 0; c < 4; ++c) accO[c] = b_u2[4 * lane + c];
        for (int kc = 0; kc < 256; kc += 32) {
#pragma unroll
            for (int l = 0; l < 16; ++l) {
                const int idx = tid + l * 256;
                ws[idx] = W_u2[(size_t)(kc + (idx >> 7)) * D + (idx & 127)];
            }
            __syncthreads();
#pragma unroll 8
            for (int k = 0; k < 32; ++k) {
                const float4 wv = *(const float4*)&ws[k * 128 + 4 * lane];
                const float a = bufU[(kc + k) * P + warp];
                accO[0] = fmaf(a, wv.x, accO[0]);
                accO[1] = fmaf(a, wv.y, accO[1]);
                accO[2] = fmaf(a, wv.z, accO[2]);
                accO[3] = fmaf(a, wv.w, accO[3]);
            }
            __syncthreads();
        }
    }
    {
        const size_t o = (size_t)(r0 + warp) * D + 4 * lane;
        const float4 sv = *(const float4*)&slots[o];
        float4 ov;
        ov.x = sv.x + accO[0];
        ov.y = sv.y + accO[1];
        ov.z = sv.z + accO[2];
        ov.w = sv.w + accO[3];
        *(float4*)&out[o] = ov;
    }
}

// ---------------------------------------------------------------------------
extern "C" void kernel_launch(void* const* d_in, const int* in_sizes, int n_in,
                              void* d_out, int out_size)
{
    const float* slots = (const float*)d_in[0];
    const float* adj   = (const float*)d_in[1];
    const float* W_m1  = (const float*)d_in[2];
    const float* b_m1  = (const float*)d_in[3];
    const float* W_m2  = (const float*)d_in[4];
    const float* b_m2  = (const float*)d_in[5];
    const float* W_u1  = (const float*)d_in[6];
    const float* b_u1  = (const float*)d_in[7];
    const float* ln_g  = (const float*)d_in[8];
    const float* ln_b  = (const float*)d_in[9];
    const float* W_u2  = (const float*)d_in[10];
    const float* b_u2  = (const float*)d_in[11];
    float* out = (float*)d_out;

    asum_kernel<<<BN / 8, 256>>>(adj);
    dim3 pg(BN / 64, 16);
    proj_kernel<<<pg, 256>>>(slots, W_m1, b_m1);
    msg_agg_kernel<<<BN / 2, 128>>>(adj);
    epilogue_kernel<<<BN / 8, 256>>>(slots, W_m2, b_m2, W_u1, b_u1,
                                     ln_g, ln_b, W_u2, b_u2, out);
}

// round 17
// speedup vs baseline: 1.0315x; 1.0315x over previous
#include <cuda_runtime.h>
#include <math.h>

#define B 8
#define N 256
#define D 128
#define H 256
#define BN (B * N)   // 2048

// Scratch (allocation-free rule: device globals), 16B aligned for vector access
__device__ __align__(16) float g_hi[BN * H];   // slots @ W_m1[:D]
__device__ __align__(16) float g_hj[BN * H];   // slots @ W_m1[D:] + b_m1
__device__ __align__(16) float g_G [BN * H];   // sum_j a_ij * gelu(hi_i + hj_j)
__device__ float g_asum[BN];                   // rowsum(adjacency)

// 2*gelu(x) via the tanh formulation + MUFU tanh.approx (sm_75+)
__device__ __forceinline__ float gelu2_tanh(float x) {
    const float xx = x * x;
    const float inner = fmaf(0.0356774081f, xx, 0.7978845608f);
    const float w = x * inner;
    float t; asm("tanh.approx.f32 %0,%1;" : "=f"(t) : "f"(w));
    return fmaf(x, t, x);                                        // x*(1+t)
}

// ---------------------------------------------------------------------------
// Kernel 0: adjacency row sums. Warp per row.
// ---------------------------------------------------------------------------
__global__ __launch_bounds__(256) void asum_kernel(const float* __restrict__ adj)
{
    const int row  = blockIdx.x * 8 + (threadIdx.x >> 5);  // b*N + n
    const int lane = threadIdx.x & 31;
    const float* arow = adj + (size_t)row * N;
    float s = 0.f;
#pragma unroll
    for (int k = 0; k < 8; ++k) s += arow[lane + k * 32];
#pragma unroll
    for (int o = 16; o > 0; o >>= 1) s += __shfl_xor_sync(~0u, s, o);
    if (lane == 0) g_asum[row] = s;
}

// ---------------------------------------------------------------------------
// Kernel 1: proj GEMM, 64x32 tiles (grid 32x16 = 512 blocks), 256 threads.
// ---------------------------------------------------------------------------
#define KC 32
__global__ __launch_bounds__(256) void proj_kernel(
    const float* __restrict__ slots, const float* __restrict__ W_m1,
    const float* __restrict__ b_m1)
{
    const int r0   = blockIdx.x * 64;
    const int part = blockIdx.y >> 3;        // 0 -> hi, 1 -> hj
    const int c0   = (blockIdx.y & 7) * 32;
    const int tid  = threadIdx.x;
    const int ty   = tid >> 4, tx = tid & 15;

    __shared__ float As[64][KC + 1];
    __shared__ float Ws[KC][33];

    float acc[4][2];
#pragma unroll
    for (int r = 0; r < 4; ++r)
#pragma unroll
        for (int c = 0; c < 2; ++c) acc[r][c] = 0.f;

    const float* wsrc = W_m1 + (size_t)(part * D) * H + c0;

    for (int kc = 0; kc < D; kc += KC) {
#pragma unroll
        for (int l = 0; l < 8; ++l) {
            const int idx = tid + l * 256;
            const int r = idx >> 5, k = idx & 31;
            As[r][k] = slots[(r0 + r) * D + kc + k];
        }
#pragma unroll
        for (int l = 0; l < 4; ++l) {
            const int idx = tid + l * 256;
            const int k = idx >> 5, c = idx & 31;
            Ws[k][c] = wsrc[(kc + k) * H + c];
        }
        __syncthreads();

#pragma unroll
        for (int k = 0; k < KC; ++k) {
            float wv[2], av[4];
#pragma unroll
            for (int c = 0; c < 2; ++c) wv[c] = Ws[k][tx + 16 * c];
#pragma unroll
            for (int r = 0; r < 4; ++r) av[r] = As[ty + 16 * r][k];
#pragma unroll
            for (int r = 0; r < 4; ++r)
#pragma unroll
                for (int c = 0; c < 2; ++c)
                    acc[r][c] = fmaf(av[r], wv[c], acc[r][c]);
        }
        __syncthreads();
    }

    if (part == 0) {
#pragma unroll
        for (int r = 0; r < 4; ++r)
#pragma unroll
            for (int c = 0; c < 2; ++c)
                g_hi[(size_t)(r0 + ty + 16 * r) * H + c0 + tx + 16 * c] = acc[r][c];
    } else {
        float bm[2];
#pragma unroll
        for (int c = 0; c < 2; ++c) bm[c] = b_m1[c0 + tx + 16 * c];
#pragma unroll
        for (int r = 0; r < 4; ++r)
#pragma unroll
            for (int c = 0; c < 2; ++c)
                g_hj[(size_t)(r0 + ty + 16 * r) * H + c0 + tx + 16 * c] = acc[r][c] + bm[c];
    }
}

// ---------------------------------------------------------------------------
// Kernel 2: G[b,i,h] = sum_j a[b,i,j] * gelu(hi[b,i,h] + hjp[b,j,h])
// 2 i-rows per block (grid 1024), 128 threads; thread owns h-pair (2t, 2t+1).
// ---------------------------------------------------------------------------
__global__ __launch_bounds__(128) void msg_agg_kernel(
    const float* __restrict__ adj)
{
    const int row0 = blockIdx.x * 2;
    const int b    = row0 >> 8;
    const int i0   = row0 & (N - 1);
    const int tid  = threadIdx.x;

    __shared__ float a_s[2][N];             // prescaled by 0.5 (gelu2 = 2*gelu)
    const float* adj_b = adj + ((size_t)b * N + i0) * N;
#pragma unroll
    for (int idx = tid; idx < 2 * N; idx += 128)
        ((float*)a_s)[idx] = 0.5f * adj_b[idx];
    __syncthreads();

    const float2* hj2 = (const float2*)(g_hj + (size_t)b * N * H) + tid;
    const float2 hi0 = ((const float2*)(g_hi + (size_t) row0      * H))[tid];
    const float2 hi1 = ((const float2*)(g_hi + (size_t)(row0 + 1) * H))[tid];

    float acc00 = 0.f, acc01 = 0.f, acc10 = 0.f, acc11 = 0.f;

#pragma unroll 4
    for (int j = 0; j < N; ++j) {
        const float2 hj = hj2[(size_t)j * (H / 2)];
        const float a0 = a_s[0][j];
        const float a1 = a_s[1][j];
        acc00 = fmaf(a0, gelu2_tanh(hi0.x + hj.x), acc00);
        acc01 = fmaf(a0, gelu2_tanh(hi0.y + hj.y), acc01);
        acc10 = fmaf(a1, gelu2_tanh(hi1.x + hj.x), acc10);
        acc11 = fmaf(a1, gelu2_tanh(hi1.y + hj.y), acc11);
    }

    float2 o0; o0.x = acc00; o0.y = acc01;
    float2 o1; o1.x = acc10; o1.y = acc11;
    ((float2*)(g_G + (size_t) row0      * H))[tid] = o0;
    ((float2*)(g_G + (size_t)(row0 + 1) * H))[tid] = o1;
}

// ---------------------------------------------------------------------------
// Kernel 3: fused epilogue v5 = v4 (R=8, transposed pitch-9 operands) with
// float4 staging + register-carried double buffer: the next weight chunk's
// 4 LDG.128 are issued right after the sync and consumed one compute-phase
// later, so staging latency hides behind FMAs; staging LSU ops drop 4x.
// ---------------------------------------------------------------------------
#define P 9
__global__ __launch_bounds__(256) void epilogue_kernel(
    const float* __restrict__ slots,
    const float* __restrict__ W_m2, const float* __restrict__ b_m2,
    const float* __restrict__ W_u1, const float* __restrict__ b_u1,
    const float* __restrict__ ln_g, const float* __restrict__ ln_b,
    const float* __restrict__ W_u2, const float* __restrict__ b_u2,
    float* __restrict__ out)
{
    const int r0  = blockIdx.x * 8;         // global row = b*N + n
    const int tid = threadIdx.x;
    const int warp = tid >> 5, lane = tid & 31;
    const int hg  = tid & 63;               // phase C: cols 4hg..4hg+3
    const int r2  = tid >> 6;               //          rows 2r2, 2r2+1

    __shared__ __align__(16) float bufA[256 * P]; // G_t -> [slots_t|agg_t]
    __shared__ __align__(16) float bufU[256 * P]; // u_t
    __shared__ __align__(16) float ws[4096];      // 16KB weight staging
    __shared__ float asum_s[8];

    // Load G transposed: bufA[k*P + row]
#pragma unroll
    for (int l = 0; l < 8; ++l) {
        const int idx = tid + l * 256;
        const int row = idx >> 8, k = idx & 255;
        bufA[k * P + row] = g_G[(size_t)(r0 + row) * H + k];
    }
    if (tid < 8) asum_s[tid] = g_asum[r0 + tid];

    // Preload first W_m2 chunk (32x128 = 4096 floats, contiguous) into regs
    float4 st[4];
#pragma unroll
    for (int l = 0; l < 4; ++l)
        st[l] = *(const float4*)&W_m2[4 * (tid + l * 256)];
    __syncthreads();

    // ---- Phase A: agg (K=256, 8 chunks of 32). row=warp, cols 4*lane.. ----
    float accA[4];
    {
#pragma unroll
        for (int c = 0; c < 4; ++c)
            accA[c] = asum_s[warp] * b_m2[4 * lane + c];
        for (int kc = 0; kc < 256; kc += 32) {
#pragma unroll
            for (int l = 0; l < 4; ++l)
                *(float4*)&ws[4 * (tid + l * 256)] = st[l];
            __syncthreads();
            if (kc + 32 < 256) {
#pragma unroll
                for (int l = 0; l < 4; ++l)
                    st[l] = *(const float4*)&W_m2[(size_t)(kc + 32) * D + 4 * (tid + l * 256)];
            } else {
                // preload first W_u1 chunk (16x256 contiguous) for Phase C
#pragma unroll
                for (int l = 0; l < 4; ++l)
                    st[l] = *(const float4*)&W_u1[4 * (tid + l * 256)];
            }
#pragma unroll 8
            for (int k = 0; k < 32; ++k) {
                const float4 wv = *(const float4*)&ws[k * 128 + 4 * lane];
                const float a = bufA[(kc + k) * P + warp];
                accA[0] = fmaf(a, wv.x, accA[0]);
                accA[1] = fmaf(a, wv.y, accA[1]);
                accA[2] = fmaf(a, wv.z, accA[2]);
                accA[3] = fmaf(a, wv.w, accA[3]);
            }
            __syncthreads();
        }
    }

    // Repack bufA: [k 0..127] = slots_t, [k 128..255] = agg_t
#pragma unroll
    for (int c = 0; c < 4; ++c)
        bufA[(128 + 4 * lane + c) * P + warp] = accA[c];
#pragma unroll
    for (int l = 0; l < 4; ++l) {
        const int idx = tid + l * 256;
        const int row = idx >> 7, dd = idx & 127;
        bufA[dd * P + row] = slots[(size_t)(r0 + row) * D + dd];
    }
    __syncthreads();

    // ---- Phase C: u = [slots|agg] @ W_u1 + b_u1 (K=256, 16 chunks of 16) ----
    float accU[2][4];
    {
#pragma unroll
        for (int c = 0; c < 4; ++c) {
            const float bu = b_u1[4 * hg + c];
            accU[0][c] = bu; accU[1][c] = bu;
        }
        for (int kc = 0; kc < 256; kc += 16) {
#pragma unroll
            for (int l = 0; l < 4; ++l)
                *(float4*)&ws[4 * (tid + l * 256)] = st[l];
            __syncthreads();
            if (kc + 16 < 256) {
#pragma unroll
                for (int l = 0; l < 4; ++l)
                    st[l] = *(const float4*)&W_u1[(size_t)(kc + 16) * H + 4 * (tid + l * 256)];
            } else {
                // preload first W_u2 chunk for Phase E
#pragma unroll
                for (int l = 0; l < 4; ++l)
                    st[l] = *(const float4*)&W_u2[4 * (tid + l * 256)];
            }
#pragma unroll 4
            for (int k = 0; k < 16; ++k) {
                const float4 wv = *(const float4*)&ws[k * 256 + 4 * hg];
                const float a0 = bufA[(kc + k) * P + 2 * r2];
                const float a1 = bufA[(kc + k) * P + 2 * r2 + 1];
                accU[0][0] = fmaf(a0, wv.x, accU[0][0]);
                accU[0][1] = fmaf(a0, wv.y, accU[0][1]);
                accU[0][2] = fmaf(a0, wv.z, accU[0][2]);
                accU[0][3] = fmaf(a0, wv.w, accU[0][3]);
                accU[1][0] = fmaf(a1, wv.x, accU[1][0]);
                accU[1][1] = fmaf(a1, wv.y, accU[1][1]);
                accU[1][2] = fmaf(a1, wv.z, accU[1][2]);
                accU[1][3] = fmaf(a1, wv.w, accU[1][3]);
            }
            __syncthreads();
        }
    }
    // store u transposed: bufU[h*P + row]
#pragma unroll
    for (int r = 0; r < 2; ++r)
#pragma unroll
        for (int c = 0; c < 4; ++c)
            bufU[(4 * hg + c) * P + 2 * r2 + r] = accU[r][c];
    __syncthreads();

    // ---- LayerNorm + tanh-gelu: warp per row ----
    {
        const int row = warp;
        float v[8];
#pragma unroll
        for (int m = 0; m < 8; ++m) v[m] = bufU[(lane + 32 * m) * P + row];
        float s = 0.f;
#pragma unroll
        for (int m = 0; m < 8; ++m) s += v[m];
#pragma unroll
        for (int o = 16; o > 0; o >>= 1) s += __shfl_xor_sync(~0u, s, o);
        const float mu = s * (1.f / H);
        float ss = 0.f;
#pragma unroll
        for (int m = 0; m < 8; ++m) { const float dd = v[m] - mu; ss += dd * dd; }
#pragma unroll
        for (int o = 16; o > 0; o >>= 1) ss += __shfl_xor_sync(~0u, ss, o);
        const float rstd = rsqrtf(ss * (1.f / H) + 1e-5f);
#pragma unroll
        for (int m = 0; m < 8; ++m) {
            const int h = lane + 32 * m;
            const float x = (v[m] - mu) * rstd * ln_g[h] + ln_b[h];
            bufU[h * P + row] = 0.5f * gelu2_tanh(x);
        }
    }
    __syncthreads();

    // ---- Phase E: out = slots + u @ W_u2 + b_u2 (K=256, 8 chunks of 32) ----
    float accO[4];
    {
#pragma unroll
        for (int c = 0; c < 4; ++c) accO[c] = b_u2[4 * lane + c];
        for (int kc = 0; kc < 256; kc += 32) {
#pragma unroll
            for (int l = 0; l < 4; ++l)
                *(float4*)&ws[4 * (tid + l * 256)] = st[l];
            __syncthreads();
            if (kc + 32 < 256) {
#pragma unroll
                for (int l = 0; l < 4; ++l)
                    st[l] = *(const float4*)&W_u2[(size_t)(kc + 32) * D + 4 * (tid + l * 256)];
            }
#pragma unroll 8
            for (int k = 0; k < 32; ++k) {
                const float4 wv = *(const float4*)&ws[k * 128 + 4 * lane];
                const float a = bufU[(kc + k) * P + warp];
                accO[0] = fmaf(a, wv.x, accO[0]);
                accO[1] = fmaf(a, wv.y, accO[1]);
                accO[2] = fmaf(a, wv.z, accO[2]);
                accO[3] = fmaf(a, wv.w, accO[3]);
            }
            __syncthreads();
        }
    }
    {
        const size_t o = (size_t)(r0 + warp) * D + 4 * lane;
        const float4 sv = *(const float4*)&slots[o];
        float4 ov;
        ov.x = sv.x + accO[0];
        ov.y = sv.y + accO[1];
        ov.z = sv.z + accO[2];
        ov.w = sv.w + accO[3];
        *(float4*)&out[o] = ov;
    }
}

// ---------------------------------------------------------------------------
extern "C" void kernel_launch(void* const* d_in, const int* in_sizes, int n_in,
                              void* d_out, int out_size)
{
    const float* slots = (const float*)d_in[0];
    const float* adj   = (const float*)d_in[1];
    const float* W_m1  = (const float*)d_in[2];
    const float* b_m1  = (const float*)d_in[3];
    const float* W_m2  = (const float*)d_in[4];
    const float* b_m2  = (const float*)d_in[5];
    const float* W_u1  = (const float*)d_in[6];
    const float* b_u1  = (const float*)d_in[7];
    const float* ln_g  = (const float*)d_in[8];
    const float* ln_b  = (const float*)d_in[9];
    const float* W_u2  = (const float*)d_in[10];
    const float* b_u2  = (const float*)d_in[11];
    float* out = (float*)d_out;

    asum_kernel<<<BN / 8, 256>>>(adj);
    dim3 pg(BN / 64, 16);
    proj_kernel<<<pg, 256>>>(slots, W_m1, b_m1);
    msg_agg_kernel<<<BN / 2, 128>>>(adj);
    epilogue_kernel<<<BN / 8, 256>>>(slots, W_m2, b_m2, W_u1, b_u1,
                                     ln_g, ln_b, W_u2, b_u2, out);
}